// round 1
// baseline (speedup 1.0000x reference)
#include <cuda_runtime.h>
#include <cuda_bf16.h>
#include <math.h>

// Problem constants
#define B_  2
#define S_  2048
#define D_  1024
#define H_  16
#define DH_ 64
#define SCALE_ 0.125f   // DH^-0.5

// Scratch (static device globals: allowed; no runtime allocation)
__device__ float g_q[(size_t)B_ * S_ * D_];
__device__ float g_k[(size_t)B_ * S_ * D_];
__device__ float g_v[(size_t)B_ * S_ * D_];
__device__ float g_ctx[(size_t)B_ * S_ * D_];
__device__ float g_attn_raw[(size_t)B_ * H_ * S_ * S_];   // 512 MB raw scores
__device__ float g_stats[(size_t)B_ * H_ * S_ * 2];       // (m, l) per row

// ---------------------------------------------------------------------------
// Generic fp32 GEMM: C[M,N] = A[M,K] @ B[N,K]^T + bias[N]
// 128x128 tile, BK=8, 256 threads, 8x8 micro-tile (split 4+4 for conflict-free
// float4 smem reads). M,N,K all multiples of 128 here -> no bounds checks.
// ---------------------------------------------------------------------------
__global__ __launch_bounds__(256) void gemm_abt_bias(
    const float* __restrict__ A, const float* __restrict__ Bm,
    const float* __restrict__ bias, float* __restrict__ C,
    int M, int N, int K)
{
    __shared__ float As[8][128];
    __shared__ float Bs[8][128];
    const int t  = threadIdx.x;
    const int tx = t & 15, ty = t >> 4;
    const int bm = blockIdx.y * 128, bn = blockIdx.x * 128;
    const int lr = t >> 1, lc = (t & 1) << 2;

    const float* Ag = A  + (size_t)(bm + lr) * K + lc;
    const float* Bg = Bm + (size_t)(bn + lr) * K + lc;

    float acc[8][8];
#pragma unroll
    for (int i = 0; i < 8; i++)
#pragma unroll
        for (int j = 0; j < 8; j++) acc[i][j] = 0.f;

    for (int k0 = 0; k0 < K; k0 += 8) {
        float4 av = *(const float4*)(Ag + k0);
        float4 bv = *(const float4*)(Bg + k0);
        __syncthreads();   // previous compute done before overwrite
        As[lc + 0][lr] = av.x; As[lc + 1][lr] = av.y;
        As[lc + 2][lr] = av.z; As[lc + 3][lr] = av.w;
        Bs[lc + 0][lr] = bv.x; Bs[lc + 1][lr] = bv.y;
        Bs[lc + 2][lr] = bv.z; Bs[lc + 3][lr] = bv.w;
        __syncthreads();
#pragma unroll
        for (int kk = 0; kk < 8; kk++) {
            float a[8], b[8];
            *(float4*)(a)     = *(const float4*)&As[kk][ty * 4];
            *(float4*)(a + 4) = *(const float4*)&As[kk][64 + ty * 4];
            *(float4*)(b)     = *(const float4*)&Bs[kk][tx * 4];
            *(float4*)(b + 4) = *(const float4*)&Bs[kk][64 + tx * 4];
#pragma unroll
            for (int i = 0; i < 8; i++)
#pragma unroll
                for (int j = 0; j < 8; j++) acc[i][j] += a[i] * b[j];
        }
    }

#pragma unroll
    for (int ib = 0; ib < 2; ib++)
#pragma unroll
        for (int ii = 0; ii < 4; ii++) {
            const int m = bm + ib * 64 + ty * 4 + ii;
#pragma unroll
            for (int jb = 0; jb < 2; jb++) {
                const int n = bn + jb * 64 + tx * 4;
                float4 o;
                o.x = acc[ib * 4 + ii][jb * 4 + 0] + bias[n + 0];
                o.y = acc[ib * 4 + ii][jb * 4 + 1] + bias[n + 1];
                o.z = acc[ib * 4 + ii][jb * 4 + 2] + bias[n + 2];
                o.w = acc[ib * 4 + ii][jb * 4 + 3] + bias[n + 3];
                *(float4*)&C[(size_t)m * N + n] = o;
            }
        }
}

// ---------------------------------------------------------------------------
// Scores kernel: per (b,h, 64-row q tile). Computes raw masked+scaled scores,
// streams them to g_attn_raw, maintains online (rowmax, sum-exp) stats.
// ---------------------------------------------------------------------------
__global__ __launch_bounds__(256) void scores_stats_kernel(
    const float* __restrict__ q, const float* __restrict__ kmat,
    const int* __restrict__ mask, float* __restrict__ raw,
    float* __restrict__ stats)
{
    __shared__ float Qs[64][65];
    __shared__ float KSs[64][65];   // K tile during compute, then score tile
    const int t  = threadIdx.x;
    const int tx = t & 15, ty = t >> 4;
    const int bh = blockIdx.y;
    const int b  = bh >> 4;      // H_=16
    const int h  = bh & 15;
    const int q0 = blockIdx.x * 64;

    // load Q tile [64 q-rows][64 dh]
    for (int i = t; i < 64 * 16; i += 256) {
        const int row = i >> 4, c = (i & 15) << 2;
        float4 vv = *(const float4*)&q[(((size_t)(b * S_ + q0 + row)) * H_ + h) * DH_ + c];
        Qs[row][c + 0] = vv.x; Qs[row][c + 1] = vv.y;
        Qs[row][c + 2] = vv.z; Qs[row][c + 3] = vv.w;
    }

    float mrun = -1e30f, lrun = 0.f;

    for (int kt = 0; kt < S_ / 64; kt++) {
        const int k0 = kt * 64;
        __syncthreads();   // previous score-tile consumers done
        for (int i = t; i < 64 * 16; i += 256) {
            const int row = i >> 4, c = (i & 15) << 2;
            float4 vv = *(const float4*)&kmat[(((size_t)(b * S_ + k0 + row)) * H_ + h) * DH_ + c];
            KSs[row][c + 0] = vv.x; KSs[row][c + 1] = vv.y;
            KSs[row][c + 2] = vv.z; KSs[row][c + 3] = vv.w;
        }
        __syncthreads();

        float acc[4][4] = {};
#pragma unroll 16
        for (int kk = 0; kk < 64; kk++) {
            float a[4], bb[4];
#pragma unroll
            for (int i = 0; i < 4; i++) a[i]  = Qs[ty * 4 + i][kk];
#pragma unroll
            for (int j = 0; j < 4; j++) bb[j] = KSs[tx * 4 + j][kk];
#pragma unroll
            for (int i = 0; i < 4; i++)
#pragma unroll
                for (int j = 0; j < 4; j++) acc[i][j] += a[i] * bb[j];
        }
        __syncthreads();   // all K-tile reads done before reuse as score tile

        // mask + scale -> score tile (reuse KSs)
#pragma unroll
        for (int i = 0; i < 4; i++) {
            const int qrow = q0 + ty * 4 + i;
            const int* mrow = &mask[((size_t)b * S_ + qrow) * S_ + k0];
#pragma unroll
            for (int j = 0; j < 4; j++) {
                float s = acc[i][j] * SCALE_;
                if (mrow[tx * 4 + j] == 0) s = -1e9f;
                KSs[ty * 4 + i][tx * 4 + j] = s;
            }
        }
        __syncthreads();

        // online stats: one thread per q-row
        if (t < 64) {
            float tm = -1e30f;
#pragma unroll 8
            for (int n = 0; n < 64; n++) tm = fmaxf(tm, KSs[t][n]);
            const float mn = fmaxf(mrun, tm);
            float add = 0.f;
#pragma unroll 8
            for (int n = 0; n < 64; n++) add += __expf(KSs[t][n] - mn);
            lrun = lrun * __expf(mrun - mn) + add;
            mrun = mn;
        }
        // stream raw scores (coalesced)
        for (int i = t; i < 4096; i += 256) {
            const int row = i >> 6, col = i & 63;
            raw[(((size_t)bh * S_) + q0 + row) * S_ + k0 + col] = KSs[row][col];
        }
    }

    if (t < 64) {
        const size_t si = ((size_t)bh * S_ + q0 + t) * 2;
        stats[si] = mrun;
        stats[si + 1] = lrun;
    }
}

// ---------------------------------------------------------------------------
// AV kernel: normalizes raw scores -> writes attn output, accumulates attn @ V
// into ctx [B,S,H,DH]. Safe in-place when attn_out == raw (same-thread RW).
// ---------------------------------------------------------------------------
__global__ __launch_bounds__(256) void av_norm_kernel(
    const float* __restrict__ raw, const float* __restrict__ stats,
    const float* __restrict__ v, float* __restrict__ attn_out,
    float* __restrict__ ctx)
{
    __shared__ float Ps[64][65];   // transposed: [k][q]
    __shared__ float Vs[64][68];   // [k][dh], padded for aligned float4
    __shared__ float sm_m[64], sm_il[64];
    const int t  = threadIdx.x;
    const int tx = t & 15, ty = t >> 4;
    const int bh = blockIdx.y;
    const int b  = bh >> 4;
    const int h  = bh & 15;
    const int q0 = blockIdx.x * 64;

    if (t < 64) {
        const size_t si = ((size_t)bh * S_ + q0 + t) * 2;
        sm_m[t]  = stats[si];
        sm_il[t] = 1.0f / stats[si + 1];
    }

    float acc[4][4] = {};
    __syncthreads();

    for (int kt = 0; kt < S_ / 64; kt++) {
        const int k0 = kt * 64;
        __syncthreads();   // previous compute done before overwriting tiles
        for (int i = t; i < 4096; i += 256) {
            const int row = i >> 6, col = i & 63;
            const size_t gi = (((size_t)bh * S_) + q0 + row) * S_ + k0 + col;
            const float p = __expf(raw[gi] - sm_m[row]) * sm_il[row];
            attn_out[gi] = p;
            Ps[col][row] = p;
        }
        for (int i = t; i < 1024; i += 256) {
            const int row = i >> 4, c = (i & 15) << 2;
            float4 vv = *(const float4*)&v[(((size_t)(b * S_ + k0 + row)) * H_ + h) * DH_ + c];
            *(float4*)&Vs[row][c] = vv;
        }
        __syncthreads();
#pragma unroll 8
        for (int n = 0; n < 64; n++) {
            float a[4];
#pragma unroll
            for (int i = 0; i < 4; i++) a[i] = Ps[n][ty * 4 + i];
            const float4 bb = *(const float4*)&Vs[n][tx * 4];
#pragma unroll
            for (int i = 0; i < 4; i++) {
                acc[i][0] += a[i] * bb.x;
                acc[i][1] += a[i] * bb.y;
                acc[i][2] += a[i] * bb.z;
                acc[i][3] += a[i] * bb.w;
            }
        }
    }

#pragma unroll
    for (int i = 0; i < 4; i++) {
        const int qrow = q0 + ty * 4 + i;
        float4 o;
        o.x = acc[i][0]; o.y = acc[i][1]; o.z = acc[i][2]; o.w = acc[i][3];
        *(float4*)&ctx[(((size_t)(b * S_ + qrow)) * H_ + h) * DH_ + tx * 4] = o;
    }
}

// ---------------------------------------------------------------------------
extern "C" void kernel_launch(void* const* d_in, const int* in_sizes, int n_in,
                              void* d_out, int out_size)
{
    const float* x    = (const float*)d_in[0];
    const int*   mask = (const int*)  d_in[1];
    const float* wq_w = (const float*)d_in[2];
    const float* wq_b = (const float*)d_in[3];
    const float* wk_w = (const float*)d_in[4];
    const float* wk_b = (const float*)d_in[5];
    const float* wv_w = (const float*)d_in[6];
    const float* wv_b = (const float*)d_in[7];
    const float* wo_w = (const float*)d_in[8];
    const float* wo_b = (const float*)d_in[9];

    float *q, *k, *v, *ctx, *attn_raw, *stats;
    cudaGetSymbolAddress((void**)&q,        g_q);
    cudaGetSymbolAddress((void**)&k,        g_k);
    cudaGetSymbolAddress((void**)&v,        g_v);
    cudaGetSymbolAddress((void**)&ctx,      g_ctx);
    cudaGetSymbolAddress((void**)&attn_raw, g_attn_raw);
    cudaGetSymbolAddress((void**)&stats,    g_stats);

    const long long CTXSZ = (long long)B_ * S_ * D_;           // 4194304
    const long long ATTSZ = (long long)B_ * H_ * S_ * S_;      // 134217728

    float* out_base = (float*)d_out;
    float* out_ptr;
    float* attn_ptr;
    if ((long long)out_size >= CTXSZ + ATTSZ) {
        out_ptr  = out_base;
        attn_ptr = out_base + CTXSZ;
    } else if ((long long)out_size == ATTSZ) {
        out_ptr  = q;            // final projection goes to scratch (unused after)
        attn_ptr = out_base;
    } else {
        out_ptr  = out_base;
        attn_ptr = attn_raw;     // in-place normalize (safe: same-thread RW)
    }

    const int M = B_ * S_;   // 4096
    const int N = D_;        // 1024
    const int K = D_;        // 1024
    dim3 gGrid(N / 128, M / 128);

    // Projections
    gemm_abt_bias<<<gGrid, 256>>>(x, wq_w, wq_b, q, M, N, K);
    gemm_abt_bias<<<gGrid, 256>>>(x, wk_w, wk_b, k, M, N, K);
    gemm_abt_bias<<<gGrid, 256>>>(x, wv_w, wv_b, v, M, N, K);

    // Scores + online softmax stats
    dim3 aGrid(S_ / 64, B_ * H_);
    scores_stats_kernel<<<aGrid, 256>>>(q, k, mask, attn_raw, stats);

    // Normalize + attn @ V
    av_norm_kernel<<<aGrid, 256>>>(attn_raw, stats, v, attn_ptr, ctx);

    // Output projection
    gemm_abt_bias<<<gGrid, 256>>>(ctx, wo_w, wo_b, out_ptr, M, N, K);
}